// round 3
// baseline (speedup 1.0000x reference)
#include <cuda_runtime.h>
#include <cstdint>
#include <math.h>

// Problem constants
#define BB      32
#define LL      32768
#define MM      32
#define DD      128
#define KK      16
#define STRIDE  8
#define PP      4095          // (L-K)/STRIDE + 1
#define KTOT    512           // M*K  (GEMM K)
#define KC      32            // K-chunk per pipeline stage
#define NCHUNK  16            // KTOT/KC
#define TILE_M  128
#define SSTRIDE 40            // smem row stride in floats (bank-conflict-free LDS.64)
#define STAGE_FLOATS (2 * 128 * SSTRIDE)   // A tile (128x40) + B tile (128x40) = 10240 floats
#define SMEM_FLOATS  (2 * STAGE_FLOATS + 256)
#define SMEM_BYTES   (SMEM_FLOATS * 4)     // 82944 B

// Reordered + tf32-pre-rounded weights: W2T[d][c], c = k_conv*32 + m
__device__ __align__(256) float W2T_buf[DD * KTOT];

__global__ void build_w2t(const float* __restrict__ conv_w) {
    int idx = blockIdx.x * blockDim.x + threadIdx.x;   // 0..65535
    int d = idx >> 9;
    int c = idx & 511;
    int m = c & 31;
    int k = c >> 5;
    float v = conv_w[d * 512 + m * 16 + k];
    uint32_t t;
    asm("cvt.rna.tf32.f32 %0, %1;" : "=r"(t) : "f"(v));
    W2T_buf[idx] = __uint_as_float(t);
}

__device__ __forceinline__ void cp16(uint32_t saddr, const float* g) {
    asm volatile("cp.async.cg.shared.global [%0], [%1], 16;" :: "r"(saddr), "l"(g));
}

__device__ __forceinline__ void mma_tf32(float* c, const uint32_t* a, uint32_t b0, uint32_t b1) {
    asm volatile(
        "mma.sync.aligned.m16n8k8.row.col.f32.tf32.tf32.f32 "
        "{%0,%1,%2,%3}, {%4,%5,%6,%7}, {%8,%9}, {%0,%1,%2,%3};"
        : "+f"(c[0]), "+f"(c[1]), "+f"(c[2]), "+f"(c[3])
        : "r"(a[0]), "r"(a[1]), "r"(a[2]), "r"(a[3]), "r"(b0), "r"(b1));
}

__global__ __launch_bounds__(256, 2)
void patch_gemm(const float* __restrict__ x, const float* __restrict__ ts,
                const float* __restrict__ conv_b, float* __restrict__ out) {
    extern __shared__ float smem[];
    float* med_s  = smem + 2 * STAGE_FLOATS;   // 128 floats
    float* bias_s = med_s + 128;               // 128 floats

    const int tid  = threadIdx.x;
    const int lane = tid & 31;
    const int warp = tid >> 5;
    const int wm   = warp >> 2;     // 0..1 : 64-row slab
    const int wn   = warp & 3;      // 0..3 : 32-col slab
    const int b    = blockIdx.y;
    const int p0   = blockIdx.x * TILE_M;

    // ---- prologue: medians (timestamps are pre-sorted -> window median = ts[8p+7]) + bias
    if (tid < 128) {
        int p = min(p0 + tid, PP - 1);
        med_s[tid]  = ts[b * LL + p * STRIDE + 7];
        bias_s[tid] = conv_b[tid];
    }

    // ---- cp.async mapping: 256 threads, each owns 4 A-rows + 4 B-rows, one 16B seg each
    const int r_base = tid >> 3;    // 0..31
    const int seg    = tid & 7;     // 0..7  (16B each -> 128B row chunk)
    uint32_t a_off[4];              // element offsets into x
    uint32_t b_off[4];              // element offsets into W2T_buf
    uint32_t a_sh[4], b_sh[4];      // shared addrs (stage 0)
    uint32_t s0 = (uint32_t)__cvta_generic_to_shared(smem);
    #pragma unroll
    for (int i = 0; i < 4; ++i) {
        int r = r_base + 32 * i;
        int p = min(p0 + r, PP - 1);                       // clamp: avoids OOB on last tile
        a_off[i] = ((uint32_t)b * LL + (uint32_t)p * 8) * 32 + seg * 4;
        b_off[i] = (uint32_t)r * 512 + seg * 4;            // d = r
        a_sh[i]  = s0 + ((uint32_t)r * SSTRIDE + seg * 4) * 4;
        b_sh[i]  = s0 + ((uint32_t)(128 * SSTRIDE) + (uint32_t)r * SSTRIDE + seg * 4) * 4;
    }

    float acc[4][4][4];
    #pragma unroll
    for (int i = 0; i < 4; ++i)
        #pragma unroll
        for (int j = 0; j < 4; ++j)
            #pragma unroll
            for (int k = 0; k < 4; ++k) acc[i][j][k] = 0.f;

    // first chunk
    {
        #pragma unroll
        for (int i = 0; i < 4; ++i) {
            cp16(a_sh[i], x + a_off[i]);
            cp16(b_sh[i], W2T_buf + b_off[i]);
        }
        asm volatile("cp.async.commit_group;");
    }

    const int mrow = wm * 64 + (lane >> 2);       // fragment base row within tile
    const int bcol = 2 * (lane & 3);              // physical col pair base within 8-group

    #pragma unroll 1
    for (int c = 0; c < NCHUNK; ++c) {
        if (c < NCHUNK - 1) {
            uint32_t so = (uint32_t)((c + 1) & 1) * (STAGE_FLOATS * 4);
            uint32_t go = (uint32_t)(c + 1) * KC;
            #pragma unroll
            for (int i = 0; i < 4; ++i) {
                cp16(a_sh[i] + so, x + a_off[i] + go);
                cp16(b_sh[i] + so, W2T_buf + b_off[i] + go);
            }
            asm volatile("cp.async.commit_group;");
            asm volatile("cp.async.wait_group 1;");
        } else {
            asm volatile("cp.async.wait_group 0;");
        }
        __syncthreads();

        const float* As = smem + (c & 1) * STAGE_FLOATS;
        const float* Bs = As + 128 * SSTRIDE;

        #pragma unroll
        for (int ks = 0; ks < 4; ++ks) {
            // A fragments: mma-k j <-> phys cols (2j, 2j+1)  => one LDS.64 per row-half
            uint32_t a[4][4];
            #pragma unroll
            for (int mf = 0; mf < 4; ++mf) {
                int r = mrow + mf * 16;
                float2 lo = *(const float2*)&As[r * SSTRIDE + ks * 8 + bcol];
                float2 hi = *(const float2*)&As[(r + 8) * SSTRIDE + ks * 8 + bcol];
                asm("cvt.rna.tf32.f32 %0, %1;" : "=r"(a[mf][0]) : "f"(lo.x));
                asm("cvt.rna.tf32.f32 %0, %1;" : "=r"(a[mf][2]) : "f"(lo.y));
                asm("cvt.rna.tf32.f32 %0, %1;" : "=r"(a[mf][1]) : "f"(hi.x));
                asm("cvt.rna.tf32.f32 %0, %1;" : "=r"(a[mf][3]) : "f"(hi.y));
            }
            #pragma unroll
            for (int nf = 0; nf < 4; ++nf) {
                int dr = wn * 32 + nf * 8 + (lane >> 2);
                float2 bb = *(const float2*)&Bs[dr * SSTRIDE + ks * 8 + bcol];
                uint32_t b0 = __float_as_uint(bb.x);   // pre-rounded tf32 (W2T)
                uint32_t b1 = __float_as_uint(bb.y);
                #pragma unroll
                for (int mf = 0; mf < 4; ++mf)
                    mma_tf32(acc[mf][nf], a[mf], b0, b1);
            }
        }
        __syncthreads();
    }

    // ---- epilogue: + bias + positional encoding (sin/cos pair per adjacent-col register pair)
    float dv[4], bia0[4], bia1[4];
    #pragma unroll
    for (int nf = 0; nf < 4; ++nf) {
        int col = wn * 32 + nf * 8 + bcol;             // even
        // div_term[col/2] = exp( col * (-ln(10000)/128) )
        dv[nf]   = expf((float)col * (-0.07195578415606393f));
        bia0[nf] = bias_s[col];
        bia1[nf] = bias_s[col + 1];
    }

    #pragma unroll
    for (int mf = 0; mf < 4; ++mf) {
        int r = mrow + mf * 16;
        #pragma unroll
        for (int h = 0; h < 2; ++h) {
            int rr = r + 8 * h;
            int p  = p0 + rr;
            if (p < PP) {
                float med = med_s[rr];
                size_t ob = ((size_t)b * PP + (size_t)p) * DD;
                #pragma unroll
                for (int nf = 0; nf < 4; ++nf) {
                    int col = wn * 32 + nf * 8 + bcol;
                    float sv, cv;
                    sincosf(med * dv[nf], &sv, &cv);
                    float2 o;
                    o.x = acc[mf][nf][2 * h + 0] + bia0[nf] + sv;
                    o.y = acc[mf][nf][2 * h + 1] + bia1[nf] + cv;
                    *(float2*)&out[ob + col] = o;
                }
            }
        }
    }
}

extern "C" void kernel_launch(void* const* d_in, const int* in_sizes, int n_in,
                              void* d_out, int out_size) {
    const float* x      = (const float*)d_in[0];
    const float* ts     = (const float*)d_in[1];
    const float* conv_w = (const float*)d_in[2];
    const float* conv_b = (const float*)d_in[3];
    float* out = (float*)d_out;

    build_w2t<<<64, 1024>>>(conv_w);

    cudaFuncSetAttribute(patch_gemm, cudaFuncAttributeMaxDynamicSharedMemorySize, SMEM_BYTES);
    dim3 grid(32, 32);   // x: M-tiles within a batch, y: batch
    patch_gemm<<<grid, 256, SMEM_BYTES>>>(x, ts, conv_b, out);
}

// round 6
// speedup vs baseline: 1.1153x; 1.1153x over previous
#include <cuda_runtime.h>
#include <cstdint>
#include <math.h>

// Problem constants
#define BB      32
#define LL      32768
#define MM      32
#define DD      128
#define KK      16
#define STRIDE  8
#define PP      4095          // (L-K)/STRIDE + 1
#define KTOT    512           // M*K  (GEMM K)
#define KC      32            // K-chunk per pipeline stage
#define NCHUNK  16            // KTOT/KC
#define TILE_M  128
// Row stride 48 floats: 48 ≡ 16 (mod 32) -> LDS.128 quarter-warp phases cover
// 2 rows x 4 quad-groups x 4 banks = all 32 banks, conflict-free.
#define SSTRIDE 48
#define STAGE_FLOATS (2 * 128 * SSTRIDE)   // A tile (128x48) + B tile (128x48)
#define SMEM_FLOATS  (2 * STAGE_FLOATS + 256)
#define SMEM_BYTES   (SMEM_FLOATS * 4)     // 99328 B -> 2 CTAs/SM

// Reordered + tf32-pre-rounded (RNA) weights: W2T[d][c], c = k_conv*32 + m
__device__ __align__(256) float W2T_buf[DD * KTOT];

__global__ void build_w2t(const float* __restrict__ conv_w) {
    int idx = blockIdx.x * blockDim.x + threadIdx.x;   // 0..65535
    int c = idx & 511, m = c & 31, k = c >> 5;
    float v = conv_w[(idx >> 9) * 512 + m * 16 + k];
    uint32_t t;
    asm("cvt.rna.tf32.f32 %0, %1;" : "=r"(t) : "f"(v));
    W2T_buf[idx] = __uint_as_float(t);
}

__device__ __forceinline__ void cp16(uint32_t saddr, const float* g) {
    asm volatile("cp.async.cg.shared.global [%0], [%1], 16;" :: "r"(saddr), "l"(g));
}

__device__ __forceinline__ void mma_tf32(float* c, const uint32_t* a, uint32_t b0, uint32_t b1) {
    asm volatile(
        "mma.sync.aligned.m16n8k8.row.col.f32.tf32.tf32.f32 "
        "{%0,%1,%2,%3}, {%4,%5,%6,%7}, {%8,%9}, {%0,%1,%2,%3};"
        : "+f"(c[0]), "+f"(c[1]), "+f"(c[2]), "+f"(c[3])
        : "r"(a[0]), "r"(a[1]), "r"(a[2]), "r"(a[3]), "r"(b0), "r"(b1));
}

__global__ __launch_bounds__(256, 2)
void patch_gemm(const float* __restrict__ x, const float* __restrict__ ts,
                const float* __restrict__ conv_b, float* __restrict__ out) {
    extern __shared__ float smem[];
    float* med_s  = smem + 2 * STAGE_FLOATS;   // 128 floats
    float* bias_s = med_s + 128;               // 128 floats

    const int tid  = threadIdx.x;
    const int lane = tid & 31;
    const int warp = tid >> 5;
    const int wm   = warp >> 2;     // 0..1 : 64-row slab
    const int wn   = warp & 3;      // 0..3 : 32-col slab
    const int b    = blockIdx.y;
    const int p0   = blockIdx.x * TILE_M;

    // ---- prologue: medians (ts pre-sorted -> window median = ts[8p+7]) + bias
    if (tid < 128) {
        int p = min(p0 + tid, PP - 1);
        med_s[tid]  = ts[b * LL + p * STRIDE + 7];
        bias_s[tid] = conv_b[tid];
    }

    // ---- cp.async mapping: 256 threads, 4 A-rows + 4 B-rows each, one 16B seg
    const int r_base = tid >> 3;    // 0..31
    const int seg    = tid & 7;     // 0..7 (16B each -> 32-float row chunk)
    uint32_t a_off[4], b_off[4];
    uint32_t a_sh[4], b_sh[4];
    uint32_t s0 = (uint32_t)__cvta_generic_to_shared(smem);
    #pragma unroll
    for (int i = 0; i < 4; ++i) {
        int r = r_base + 32 * i;
        int p = min(p0 + r, PP - 1);
        a_off[i] = ((uint32_t)b * LL + (uint32_t)p * 8) * 32 + seg * 4;
        b_off[i] = (uint32_t)r * 512 + seg * 4;            // d = r
        a_sh[i]  = s0 + ((uint32_t)r * SSTRIDE + seg * 4) * 4;
        b_sh[i]  = s0 + ((uint32_t)(128 * SSTRIDE) + (uint32_t)r * SSTRIDE + seg * 4) * 4;
    }

    float acc[4][4][4];
    #pragma unroll
    for (int i = 0; i < 4; ++i)
        #pragma unroll
        for (int j = 0; j < 4; ++j)
            #pragma unroll
            for (int k = 0; k < 4; ++k) acc[i][j][k] = 0.f;

    // first chunk
    #pragma unroll
    for (int i = 0; i < 4; ++i) {
        cp16(a_sh[i], x + a_off[i]);
        cp16(b_sh[i], W2T_buf + b_off[i]);
    }
    asm volatile("cp.async.commit_group;");

    const int mrow = wm * 64 + (lane >> 2);   // fragment base row within tile
    const int qoff = 4 * (lane & 3);          // quad's 4-float group within 16-col block

    #pragma unroll 1
    for (int c = 0; c < NCHUNK; ++c) {
        if (c < NCHUNK - 1) {
            uint32_t so = (uint32_t)((c + 1) & 1) * (STAGE_FLOATS * 4);
            uint32_t go = (uint32_t)(c + 1) * KC;
            #pragma unroll
            for (int i = 0; i < 4; ++i) {
                cp16(a_sh[i] + so, x + a_off[i] + go);
                cp16(b_sh[i] + so, W2T_buf + b_off[i] + go);
            }
            asm volatile("cp.async.commit_group;");
            asm volatile("cp.async.wait_group 1;");
        } else {
            asm volatile("cp.async.wait_group 0;");
        }
        __syncthreads();

        const float* As = smem + (c & 1) * STAGE_FLOATS;
        const float* Bs = As + 128 * SSTRIDE;

        #pragma unroll
        for (int blk = 0; blk < 2; ++blk) {
            // A: one LDS.128 per 8-row group per block (rows r and r+8)
            float4 alo[4], ahi[4];
            #pragma unroll
            for (int mf = 0; mf < 4; ++mf) {
                int r = mrow + mf * 16;
                alo[mf] = *(const float4*)&As[r * SSTRIDE + blk * 16 + qoff];
                ahi[mf] = *(const float4*)&As[(r + 8) * SSTRIDE + blk * 16 + qoff];
            }
            // B: one LDS.128 per 8-col group per block
            float4 bf[4];
            #pragma unroll
            for (int nf = 0; nf < 4; ++nf) {
                int dr = wn * 32 + nf * 8 + (lane >> 2);
                bf[nf] = *(const float4*)&Bs[dr * SSTRIDE + blk * 16 + qoff];
            }
            // 2 mma-k steps per block: step s uses float4 components {2s, 2s+1}
            #pragma unroll
            for (int s = 0; s < 2; ++s) {
                #pragma unroll
                for (int nf = 0; nf < 4; ++nf) {
                    const float* bp = (const float*)&bf[nf];
                    uint32_t b0 = __float_as_uint(bp[2 * s + 0]);  // pre-rounded tf32
                    uint32_t b1 = __float_as_uint(bp[2 * s + 1]);
                    #pragma unroll
                    for (int mf = 0; mf < 4; ++mf) {
                        const float* lp = (const float*)&alo[mf];
                        const float* hp = (const float*)&ahi[mf];
                        uint32_t a[4];   // raw f32 bits: HW truncates to tf32
                        a[0] = __float_as_uint(lp[2 * s + 0]);
                        a[1] = __float_as_uint(hp[2 * s + 0]);
                        a[2] = __float_as_uint(lp[2 * s + 1]);
                        a[3] = __float_as_uint(hp[2 * s + 1]);
                        mma_tf32(acc[mf][nf], a, b0, b1);
                    }
                }
            }
        }
        __syncthreads();
    }

    // ---- epilogue: + bias + positional encoding ----
    const int bcol = 2 * (lane & 3);   // C-fragment col pair base (unchanged mapping)
    float dv[4], bia0[4], bia1[4];
    #pragma unroll
    for (int nf = 0; nf < 4; ++nf) {
        int col = wn * 32 + nf * 8 + bcol;             // even
        dv[nf]   = expf((float)col * (-0.07195578415606393f));  // div_term[col/2]
        bia0[nf] = bias_s[col];
        bia1[nf] = bias_s[col + 1];
    }

    #pragma unroll
    for (int mf = 0; mf < 4; ++mf) {
        int r = mrow + mf * 16;
        #pragma unroll
        for (int h = 0; h < 2; ++h) {
            int rr = r + 8 * h;
            int p  = p0 + rr;
            if (p < PP) {
                float med = med_s[rr];
                size_t ob = ((size_t)b * PP + (size_t)p) * DD;
                #pragma unroll
                for (int nf = 0; nf < 4; ++nf) {
                    int col = wn * 32 + nf * 8 + bcol;
                    float sv, cv;
                    sincosf(med * dv[nf], &sv, &cv);
                    float2 o;
                    o.x = acc[mf][nf][2 * h + 0] + bia0[nf] + sv;
                    o.y = acc[mf][nf][2 * h + 1] + bia1[nf] + cv;
                    *(float2*)&out[ob + col] = o;
                }
            }
        }
    }
}

extern "C" void kernel_launch(void* const* d_in, const int* in_sizes, int n_in,
                              void* d_out, int out_size) {
    const float* x      = (const float*)d_in[0];
    const float* ts     = (const float*)d_in[1];
    const float* conv_w = (const float*)d_in[2];
    const float* conv_b = (const float*)d_in[3];
    float* out = (float*)d_out;

    build_w2t<<<64, 1024>>>(conv_w);

    cudaFuncSetAttribute(patch_gemm, cudaFuncAttributeMaxDynamicSharedMemorySize, SMEM_BYTES);
    dim3 grid(32, 32);   // x: M-tiles within a batch, y: batch
    patch_gemm<<<grid, 256, SMEM_BYTES>>>(x, ts, conv_b, out);
}

// round 8
// speedup vs baseline: 1.1777x; 1.0560x over previous
#include <cuda_runtime.h>
#include <cuda_fp16.h>
#include <cstdint>
#include <math.h>

#define BB      32
#define LL      32768
#define PP      4095
#define DD      128
#define KTOT    512
#define KC      64
#define NCHUNK  8
#define TILE_M  128
#define STAGE_BYTES 32768
#define TBL_OFF     65536
#define SMEM_BYTES  (TBL_OFF + 1536)

// Prebuilt fp16 B, physical smem layout (virtual-k interleave + parity slot swizzle) baked in.
__device__ __align__(256) __half W2H_buf[DD * KTOT];

__global__ void build_w2h(const float* __restrict__ conv_w) {
    int idx = blockIdx.x * blockDim.x + threadIdx.x;   // 0..65535
    int d = idx >> 9, j = idx & 511;
    int c = j >> 6, rem = j & 63;
    int pos = rem >> 3, o = rem & 7;
    int g = pos ^ (4 * (d & 1));          // undo parity slot swizzle
    int q = g & 3, sb = 2 * (g >> 2);
    int s = sb + (o >> 2);
    int v = c * 64 + 16 * s + 2 * q + 8 * ((o >> 1) & 1) + (o & 1);
    int kk = v >> 5, m = v & 31;
    W2H_buf[idx] = __float2half_rn(conv_w[d * 512 + m * 16 + kk]);
}

__device__ __forceinline__ void cp16(uint32_t saddr, const void* g) {
    asm volatile("cp.async.cg.shared.global [%0], [%1], 16;" :: "r"(saddr), "l"(g));
}

#define LDS128(v, addr) \
    asm volatile("ld.shared.v4.b32 {%0,%1,%2,%3}, [%4];" \
        : "=r"((v).x), "=r"((v).y), "=r"((v).z), "=r"((v).w) : "r"(addr))

__device__ __forceinline__ void mma16816(float* c, uint32_t a0, uint32_t a1,
                                         uint32_t a2, uint32_t a3,
                                         uint32_t b0, uint32_t b1) {
    asm volatile(
        "mma.sync.aligned.m16n8k16.row.col.f32.f16.f16.f32 "
        "{%0,%1,%2,%3}, {%4,%5,%6,%7}, {%8,%9}, {%0,%1,%2,%3};"
        : "+f"(c[0]), "+f"(c[1]), "+f"(c[2]), "+f"(c[3])
        : "r"(a0), "r"(a1), "r"(a2), "r"(a3), "r"(b0), "r"(b1));
}

__device__ __forceinline__ void cvtsts(uint32_t addr, const float2* f) {
    uint32_t h0, h1, h2, h3;
    asm("cvt.rn.f16x2.f32 %0, %1, %2;" : "=r"(h0) : "f"(f[0].y), "f"(f[0].x));
    asm("cvt.rn.f16x2.f32 %0, %1, %2;" : "=r"(h1) : "f"(f[1].y), "f"(f[1].x));
    asm("cvt.rn.f16x2.f32 %0, %1, %2;" : "=r"(h2) : "f"(f[2].y), "f"(f[2].x));
    asm("cvt.rn.f16x2.f32 %0, %1, %2;" : "=r"(h3) : "f"(f[3].y), "f"(f[3].x));
    asm volatile("st.shared.v4.b32 [%0], {%1,%2,%3,%4};"
                 :: "r"(addr), "r"(h0), "r"(h1), "r"(h2), "r"(h3));
}

__device__ __forceinline__ void ldg_unit(float2* f, const float* gp) {
    f[0] = *(const float2*)(gp);
    f[1] = *(const float2*)(gp + 8);
    f[2] = *(const float2*)(gp + 16);
    f[3] = *(const float2*)(gp + 24);
}

__global__ __launch_bounds__(256, 2)
void patch_gemm(const float* __restrict__ x, const float* __restrict__ ts,
                const float* __restrict__ conv_b, float* __restrict__ out) {
    extern __shared__ char smem[];
    const uint32_t s0 = (uint32_t)__cvta_generic_to_shared(smem);
    float* med_s  = (float*)(smem + TBL_OFF);
    float* bias_s = med_s + 128;

    const int tid  = threadIdx.x;
    const int lane = tid & 31;
    const int warp = tid >> 5;
    const int wm   = warp >> 2;
    const int wn   = warp & 3;
    const int b    = blockIdx.y;
    const int p0   = blockIdx.x * TILE_M;

    if (tid < 128) {
        int p = min(p0 + tid, PP - 1);
        med_s[tid]  = ts[b * LL + p * 8 + 7];   // sorted ts -> window median
        bias_s[tid] = conv_b[tid];
    }

    // producer constants
    const int pg    = tid & 7;
    const int prow0 = tid >> 3;
    const int sboff = 32 * (pg >> 2) + 2 * (pg & 3);
    const float* abase[4];
    uint32_t asts_rel[4];
    #pragma unroll
    for (int k = 0; k < 4; ++k) {
        int r = prow0 + 32 * k;
        int p = min(p0 + r, PP - 1);
        abase[k] = x + (size_t)(b * LL + 8 * p) * 32 + sboff;
        asts_rel[k] = (uint32_t)(r * 128 + ((pg ^ (4 * (r & 1))) * 16));
    }
    const int brow = tid >> 1;
    const char* bsrc = (const char*)W2H_buf + brow * 1024 + (tid & 1) * 64;
    const uint32_t bdst_rel = 16384u + (uint32_t)(brow * 128 + (tid & 1) * 64);

    // consumer fragment offsets (stage-relative)
    // group (j, lq) of row with parity rho sits at slot  lq + 4*((j ^ rho) & 1)
    const int laneRow = lane >> 2, lq = lane & 3, par = laneRow & 1;
    uint32_t aoff_lo[2], aoff_hi[2], boff[2];
    #pragma unroll
    for (int j = 0; j < 2; ++j) {
        aoff_lo[j] = (uint32_t)((wm * 64 + laneRow) * 128 + (lq ^ (4 * ((j ^ par) & 1))) * 16);
        aoff_hi[j] = (uint32_t)((wm * 64 + laneRow + 8) * 128 + (lq ^ (4 * ((j ^ par) & 1))) * 16);  // FIX: row+8 has SAME parity
        boff[j]    = 16384u + (uint32_t)((wn * 32 + laneRow) * 128 + (lq ^ (4 * ((j ^ par) & 1))) * 16);
    }

    float acc[4][4][4];
    #pragma unroll
    for (int i = 0; i < 4; ++i)
        #pragma unroll
        for (int j = 0; j < 4; ++j)
            #pragma unroll
            for (int k = 0; k < 4; ++k) acc[i][j][k] = 0.f;

    // prologue: fill stage 0 with chunk 0
    {
        float2 fP[4];
        #pragma unroll
        for (int k = 0; k < 4; ++k) {
            ldg_unit(fP, abase[k]);
            cvtsts(s0 + asts_rel[k], fP);
        }
        #pragma unroll
        for (int jj = 0; jj < 4; ++jj) cp16(s0 + bdst_rel + jj * 16, bsrc + jj * 16);
        asm volatile("cp.async.commit_group;");
        asm volatile("cp.async.wait_group 0;");
    }
    __syncthreads();

    #pragma unroll 1
    for (int c = 0; c < NCHUNK; ++c) {
        const uint32_t stg = s0 + (uint32_t)(c & 1) * STAGE_BYTES;
        const uint32_t nst = s0 + (uint32_t)((c + 1) & 1) * STAGE_BYTES;
        const bool more = (c + 1 < NCHUNK);

        float2 fA[2][4];
        if (more) {
            ldg_unit(fA[0], abase[0] + (c + 1) * KC);
            ldg_unit(fA[1], abase[1] + (c + 1) * KC);
            const char* bs = bsrc + (c + 1) * 128;
            #pragma unroll
            for (int jj = 0; jj < 4; ++jj) cp16(nst + bdst_rel + jj * 16, bs + jj * 16);
            asm volatile("cp.async.commit_group;");
        }

        // j = 0
        {
            uint4 alo[4], ahi[4];
            #pragma unroll
            for (int mf = 0; mf < 4; ++mf) {
                LDS128(alo[mf], stg + aoff_lo[0] + mf * 2048);
                LDS128(ahi[mf], stg + aoff_hi[0] + mf * 2048);
            }
            #pragma unroll
            for (int nf = 0; nf < 4; ++nf) {
                uint4 bf;
                LDS128(bf, stg + boff[0] + nf * 1024);
                #pragma unroll
                for (int mf = 0; mf < 4; ++mf) {
                    mma16816(acc[mf][nf], alo[mf].x, ahi[mf].x, alo[mf].y, ahi[mf].y, bf.x, bf.y);
                    mma16816(acc[mf][nf], alo[mf].z, ahi[mf].z, alo[mf].w, ahi[mf].w, bf.z, bf.w);
                }
            }
        }

        float2 fB[2][4];
        if (more) {
            cvtsts(nst + asts_rel[0], fA[0]);
            cvtsts(nst + asts_rel[1], fA[1]);
            ldg_unit(fB[0], abase[2] + (c + 1) * KC);
            ldg_unit(fB[1], abase[3] + (c + 1) * KC);
        }

        // j = 1
        {
            uint4 alo[4], ahi[4];
            #pragma unroll
            for (int mf = 0; mf < 4; ++mf) {
                LDS128(alo[mf], stg + aoff_lo[1] + mf * 2048);
                LDS128(ahi[mf], stg + aoff_hi[1] + mf * 2048);
            }
            #pragma unroll
            for (int nf = 0; nf < 4; ++nf) {
                uint4 bf;
                LDS128(bf, stg + boff[1] + nf * 1024);
                #pragma unroll
                for (int mf = 0; mf < 4; ++mf) {
                    mma16816(acc[mf][nf], alo[mf].x, ahi[mf].x, alo[mf].y, ahi[mf].y, bf.x, bf.y);
                    mma16816(acc[mf][nf], alo[mf].z, ahi[mf].z, alo[mf].w, ahi[mf].w, bf.z, bf.w);
                }
            }
        }

        if (more) {
            cvtsts(nst + asts_rel[2], fB[0]);
            cvtsts(nst + asts_rel[3], fB[1]);
            asm volatile("cp.async.wait_group 0;");
        }
        __syncthreads();
    }

    // epilogue: + bias + positional encoding
    const int mrow = wm * 64 + laneRow;
    const int bcol = 2 * lq;
    float dv[4], bia0[4], bia1[4];
    #pragma unroll
    for (int nf = 0; nf < 4; ++nf) {
        int col = wn * 32 + nf * 8 + bcol;
        dv[nf]   = expf((float)col * (-0.07195578415606393f));
        bia0[nf] = bias_s[col];
        bia1[nf] = bias_s[col + 1];
    }

    #pragma unroll
    for (int mf = 0; mf < 4; ++mf) {
        int r = mrow + mf * 16;
        #pragma unroll
        for (int h = 0; h < 2; ++h) {
            int rr = r + 8 * h;
            int p  = p0 + rr;
            if (p < PP) {
                float med = med_s[rr];
                size_t ob = ((size_t)b * PP + (size_t)p) * DD;
                #pragma unroll
                for (int nf = 0; nf < 4; ++nf) {
                    int col = wn * 32 + nf * 8 + bcol;
                    float sv, cv;
                    sincosf(med * dv[nf], &sv, &cv);
                    float2 o;
                    o.x = acc[mf][nf][2 * h + 0] + bia0[nf] + sv;
                    o.y = acc[mf][nf][2 * h + 1] + bia1[nf] + cv;
                    *(float2*)&out[ob + col] = o;
                }
            }
        }
    }
}

extern "C" void kernel_launch(void* const* d_in, const int* in_sizes, int n_in,
                              void* d_out, int out_size) {
    const float* x      = (const float*)d_in[0];
    const float* ts     = (const float*)d_in[1];
    const float* conv_w = (const float*)d_in[2];
    const float* conv_b = (const float*)d_in[3];
    float* out = (float*)d_out;

    build_w2h<<<64, 1024>>>(conv_w);

    cudaFuncSetAttribute(patch_gemm, cudaFuncAttributeMaxDynamicSharedMemorySize, SMEM_BYTES);
    dim3 grid(32, 32);
    patch_gemm<<<grid, 256, SMEM_BYTES>>>(x, ts, conv_b, out);
}

// round 12
// speedup vs baseline: 1.4298x; 1.2141x over previous
#include <cuda_runtime.h>
#include <cuda_fp16.h>
#include <cstdint>
#include <math.h>

#define BB      32
#define LL      32768
#define PP      4095
#define DD      128
#define KTOT    512
#define KCF     64            // floats (virtual k) per chunk = 128B/row fp16
#define NCHUNK  8
#define TILE_M  128
#define ASTAGE  16384         // A stage bytes (128 rows x 128B)
#define BSTAGE  16384
#define B_OFF   32768         // A: 2 stages at 0; B: 3 stages at 32768
#define TBL_OFF 81920
#define SMEM_BYTES (TBL_OFF + 1024)

// Prebuilt fp16 B, plain v-order: W2H[d*512 + k*32 + m]
__device__ __align__(256) __half W2H_buf[DD * KTOT];

__global__ void build_w2h(const float* __restrict__ conv_w) {
    int idx = blockIdx.x * blockDim.x + threadIdx.x;   // 0..65535
    int d = idx >> 9, j = idx & 511;
    int k = j >> 5, m = j & 31;
    W2H_buf[idx] = __float2half_rn(conv_w[d * 512 + m * 16 + k]);
}

__device__ __forceinline__ void cp16(uint32_t saddr, const void* g) {
    asm volatile("cp.async.cg.shared.global [%0], [%1], 16;" :: "r"(saddr), "l"(g));
}

#define LDSM4(r0, r1, r2, r3, addr) \
    asm volatile("ldmatrix.sync.aligned.m8n8.x4.shared.b16 {%0,%1,%2,%3}, [%4];" \
        : "=r"(r0), "=r"(r1), "=r"(r2), "=r"(r3) : "r"(addr))

__device__ __forceinline__ void mma16816(float* c, uint32_t a0, uint32_t a1,
                                         uint32_t a2, uint32_t a3,
                                         uint32_t b0, uint32_t b1) {
    asm volatile(
        "mma.sync.aligned.m16n8k16.row.col.f32.f16.f16.f32 "
        "{%0,%1,%2,%3}, {%4,%5,%6,%7}, {%8,%9}, {%0,%1,%2,%3};"
        : "+f"(c[0]), "+f"(c[1]), "+f"(c[2]), "+f"(c[3])
        : "r"(a0), "r"(a1), "r"(a2), "r"(a3), "r"(b0), "r"(b1));
}

// convert 4 consecutive f32 -> 4 halves, store 8B to smem
__device__ __forceinline__ void cvtsts64(uint32_t addr, float4 f) {
    uint32_t h0, h1;
    asm("cvt.rn.f16x2.f32 %0, %1, %2;" : "=r"(h0) : "f"(f.y), "f"(f.x));
    asm("cvt.rn.f16x2.f32 %0, %1, %2;" : "=r"(h1) : "f"(f.w), "f"(f.z));
    asm volatile("st.shared.v2.b32 [%0], {%1,%2};" :: "r"(addr), "r"(h0), "r"(h1));
}

__global__ __launch_bounds__(256, 2)
void patch_gemm(const float* __restrict__ x, const float* __restrict__ ts,
                const float* __restrict__ conv_b, float* __restrict__ out) {
    extern __shared__ char smem[];
    const uint32_t s0 = (uint32_t)__cvta_generic_to_shared(smem);
    float* med_s  = (float*)(smem + TBL_OFF);
    float* bias_s = med_s + 128;

    const int tid  = threadIdx.x;
    const int lane = tid & 31;
    const int warp = tid >> 5;
    const int wm   = warp >> 2;
    const int wn   = warp & 3;
    const int b    = blockIdx.y;
    const int p0   = blockIdx.x * TILE_M;

    if (tid < 128) {
        int p = min(p0 + tid, PP - 1);
        med_s[tid]  = ts[b * LL + p * 8 + 7];   // sorted ts -> window median
        bias_s[tid] = conv_b[tid];
    }

    // ---- producer A: thread = (row trow, 16B slot tslot); 8 units = rows trow+16i ----
    const int trow  = tid >> 4;          // 0..15
    const int tslot = tid & 15;          // 0..15 (4 floats each)
    const float* ap0 = x + ((size_t)b * LL + 8 * (size_t)(p0 + trow)) * 32 + tslot * 4;
    // unit i advances 16 patches = 4096 floats; clamp only p==4095 (last tile, row 127)
    const float* ap7 = ap0 + 7 * 4096 - ((p0 + trow + 112 > PP - 1) ? 256 : 0);
    const int ag  = tslot >> 1;          // granule within row
    const int ahg = tslot & 1;           // 8B half within granule
    const uint32_t dstA0 = (uint32_t)(trow * 128 + ((ag ^ (trow & 7)) << 4) + ahg * 8);

    // ---- producer B: thread = (row trB, granule pair) ----
    const int trB = tid >> 1;
    const int gp  = (tid & 1) * 4;
    const __half* bp0 = W2H_buf + trB * 512 + gp * 8;
    uint32_t dstB[4];
    #pragma unroll
    for (int i = 0; i < 4; ++i)
        dstB[i] = (uint32_t)(trB * 128 + (((gp + i) ^ (trB & 7)) << 4));

    // ---- consumer lane constants ----
    const int laneRow = lane >> 2, lq = lane & 3;
    const int row_off = (lane & 7) + ((lane >> 3) & 1) * 8;
    const uint32_t khalf = (uint32_t)(lane >> 4);
    const uint32_t sig   = (uint32_t)(lane & 7);
    const uint32_t aBase = (uint32_t)((wm * 64 + row_off) * 128);
    const uint32_t bBase = (uint32_t)((wn * 32 + row_off) * 128);

    float acc[4][4][4];
    #pragma unroll
    for (int i = 0; i < 4; ++i)
        #pragma unroll
        for (int j = 0; j < 4; ++j)
            #pragma unroll
            for (int k = 0; k < 4; ++k) acc[i][j][k] = 0.f;

    // ---- prologue: B chunks 0,1 via cp.async; A chunk 0 via LDG+cvt+STS ----
    #pragma unroll
    for (int s = 0; s < 2; ++s) {
        uint32_t d = s0 + B_OFF + (uint32_t)s * BSTAGE;
        const __half* src = bp0 + s * KCF;
        #pragma unroll
        for (int i = 0; i < 4; ++i) cp16(d + dstB[i], src + i * 8);
        asm volatile("cp.async.commit_group;");
    }
    #pragma unroll
    for (int i = 0; i < 8; ++i) {
        const float* p = (i < 7) ? (ap0 + i * 4096) : ap7;
        cvtsts64(s0 + dstA0 + (uint32_t)i * 2048, *(const float4*)p);
    }
    asm volatile("cp.async.wait_group 1;");
    __syncthreads();

#define KX(kt) ((((kt) * 2 + khalf) ^ sig) << 4)
#define COMPUTE(kt) do {                                                        \
    const uint32_t kxv = KX(kt);                                                \
    uint32_t a0[4], a1[4], a2[4], a3[4];                                        \
    _Pragma("unroll")                                                           \
    for (int mf = 0; mf < 4; ++mf)                                              \
        LDSM4(a0[mf], a1[mf], a2[mf], a3[mf], sA + aBase + mf * 2048 + kxv);    \
    _Pragma("unroll")                                                           \
    for (int np = 0; np < 2; ++np) {                                            \
        uint32_t b0, b1, b2, b3;                                                \
        LDSM4(b0, b1, b2, b3, sB + bBase + (uint32_t)np * 2048 + kxv);          \
        _Pragma("unroll")                                                       \
        for (int mf = 0; mf < 4; ++mf) {                                        \
            mma16816(acc[mf][np * 2 + 0], a0[mf], a1[mf], a2[mf], a3[mf], b0, b2); \
            mma16816(acc[mf][np * 2 + 1], a0[mf], a1[mf], a2[mf], a3[mf], b1, b3); \
        }                                                                       \
    }                                                                           \
} while (0)

    #pragma unroll 1
    for (int c = 0; c < NCHUNK; ++c) {
        const uint32_t sA  = s0 + (uint32_t)(c & 1) * ASTAGE;
        const uint32_t sAn = s0 + (uint32_t)((c + 1) & 1) * ASTAGE;
        const uint32_t sB  = s0 + B_OFF + (uint32_t)(c % 3) * BSTAGE;
        const bool more = (c < NCHUNK - 1);

        if (c + 2 < NCHUNK) {
            uint32_t d = s0 + B_OFF + (uint32_t)((c + 2) % 3) * BSTAGE;
            const __half* src = bp0 + (c + 2) * KCF;
            #pragma unroll
            for (int i = 0; i < 4; ++i) cp16(d + dstB[i], src + i * 8);
            asm volatile("cp.async.commit_group;");
        }

        float4 f0[4];
        if (more) {
            #pragma unroll
            for (int i = 0; i < 4; ++i)
                f0[i] = *(const float4*)(ap0 + i * 4096 + (c + 1) * KCF);
        }

        COMPUTE(0);
        COMPUTE(1);

        float4 f1[4];
        if (more) {
            #pragma unroll
            for (int i = 0; i < 4; ++i)
                cvtsts64(sAn + dstA0 + (uint32_t)i * 2048, f0[i]);
            #pragma unroll
            for (int i = 4; i < 8; ++i) {
                const float* p = (i < 7) ? (ap0 + i * 4096) : ap7;
                f1[i - 4] = *(const float4*)(p + (c + 1) * KCF);
            }
        }

        COMPUTE(2);
        COMPUTE(3);

        if (more) {
            #pragma unroll
            for (int i = 4; i < 8; ++i)
                cvtsts64(sAn + dstA0 + (uint32_t)i * 2048, f1[i - 4]);
        }

        if (c + 2 < NCHUNK) { asm volatile("cp.async.wait_group 1;"); }
        else                { asm volatile("cp.async.wait_group 0;"); }
        __syncthreads();
    }

    // ---- epilogue: + bias + positional encoding ----
    const int mrow = wm * 64 + laneRow;
    const int bcol = 2 * lq;
    float dv[4], bia0[4], bia1[4];
    #pragma unroll
    for (int nf = 0; nf < 4; ++nf) {
        int col = wn * 32 + nf * 8 + bcol;
        dv[nf]   = expf((float)col * (-0.07195578415606393f));
        bia0[nf] = bias_s[col];
        bia1[nf] = bias_s[col + 1];
    }

    #pragma unroll
    for (int mf = 0; mf < 4; ++mf) {
        int r = mrow + mf * 16;
        #pragma unroll
        for (int h = 0; h < 2; ++h) {
            int rr = r + 8 * h;
            int p  = p0 + rr;
            if (p < PP) {
                float med = med_s[rr];
                size_t ob = ((size_t)b * PP + (size_t)p) * DD;
                #pragma unroll
                for (int nf = 0; nf < 4; ++nf) {
                    int col = wn * 32 + nf * 8 + bcol;
                    float sv, cv;
                    sincosf(med * dv[nf], &sv, &cv);
                    float2 o;
                    o.x = acc[mf][nf][2 * h + 0] + bia0[nf] + sv;
                    o.y = acc[mf][nf][2 * h + 1] + bia1[nf] + cv;
                    *(float2*)&out[ob + col] = o;
                }
            }
        }
    }
}

extern "C" void kernel_launch(void* const* d_in, const int* in_sizes, int n_in,
                              void* d_out, int out_size) {
    const float* x      = (const float*)d_in[0];
    const float* ts     = (const float*)d_in[1];
    const float* conv_w = (const float*)d_in[2];
    const float* conv_b = (const float*)d_in[3];
    float* out = (float*)d_out;

    build_w2h<<<64, 1024>>>(conv_w);

    cudaFuncSetAttribute(patch_gemm, cudaFuncAttributeMaxDynamicSharedMemorySize, SMEM_BYTES);
    dim3 grid(32, 32);
    patch_gemm<<<grid, 256, SMEM_BYTES>>>(x, ts, conv_b, out);
}